// round 15
// baseline (speedup 1.0000x reference)
#include <cuda_runtime.h>
#include <cstdint>

#define PI  3.14159265358979323846f
#define PIH 1.57079632679489662f
#define IR2 0.70710678118654752f

typedef unsigned long long u64;

// packed-f32x2 constants (bit patterns of {lo,hi})
#define ONE2   0x3F8000003F800000ull
#define MONE2  0xBF800000BF800000ull
#define TWO2   0x4000000040000000ull
#define MTWO2  0xC0000000C0000000ull
#define IR22   0x3F3504F33F3504F3ull
#define MIR22  0xBF3504F3BF3504F3ull

// 16 MB scratch between passes (fits in L2)
__device__ float4 g_scr[1 << 20];

__device__ __forceinline__ float sin_ap(float x){ float y; asm("sin.approx.f32 %0, %1;" : "=f"(y) : "f"(x)); return y; }
__device__ __forceinline__ float sqrt_ap(float x){ float y; asm("sqrt.approx.f32 %0, %1;" : "=f"(y) : "f"(x)); return y; }
__device__ __forceinline__ u64 pk(float lo, float hi){ u64 r; asm("mov.b64 %0, {%1, %2};" : "=l"(r) : "f"(lo), "f"(hi)); return r; }
__device__ __forceinline__ void upk(float& lo, float& hi, u64 v){ asm("mov.b64 {%0, %1}, %2;" : "=f"(lo), "=f"(hi) : "l"(v)); }
__device__ __forceinline__ u64 mul2(u64 a, u64 b){ u64 d; asm("mul.rn.f32x2 %0, %1, %2;" : "=l"(d) : "l"(a), "l"(b)); return d; }
__device__ __forceinline__ u64 add2(u64 a, u64 b){ u64 d; asm("add.rn.f32x2 %0, %1, %2;" : "=l"(d) : "l"(a), "l"(b)); return d; }
__device__ __forceinline__ u64 fma2(u64 a, u64 b, u64 c){ u64 d; asm("fma.rn.f32x2 %0, %1, %2, %3;" : "=l"(d) : "l"(a), "l"(b), "l"(c)); return d; }

// conflict-free for float4 tiles at the strided patterns used
__device__ __forceinline__ int swz(int r){ return r ^ ((r >> 4) & 3) ^ (((r >> 5) & 3) << 2); }

// packed squared-magnitude butterfly on 2 lanes; sqrt/clamp scalar per half
__device__ __forceinline__ void bfly2(u64& Se, u64& So, u64 c){
    u64 p = mul2(Se, So);
    float px, py; upk(px, py, p);
    float rx = sqrt_ap(fmaxf(px, 0.f));
    float ry = sqrt_ap(fmaxf(py, 0.f));
    u64 T  = mul2(c, pk(rx, ry));
    u64 Sp = add2(Se, So);
    Se = fma2(TWO2,  T, Sp);
    So = fma2(MTWO2, T, Sp);
}

struct Coef2 { u64 c1, cH, msH, q0, q1, q2, q3; };

// packed radix-8 twiddles from packed quarter-angle (s4, c4)
__device__ __forceinline__ Coef2 mkcoef2(u64 s4, u64 c4){
    Coef2 k;
    u64 t  = mul2(s4, c4);
    u64 sH = add2(t, t);
    u64 cH = fma2(MTWO2, mul2(s4, s4), ONE2);
    k.c1  = fma2(TWO2, mul2(cH, cH), MONE2);
    k.cH  = cH;
    k.msH = mul2(MONE2, sH);
    k.q0  = c4;
    u64 ms4 = mul2(MONE2, s4);
    k.q1  = mul2(add2(c4, ms4), IR22);
    k.q2  = ms4;
    k.q3  = mul2(add2(c4, s4), MIR22);
    return k;
}

// Pass A: stages pair ascending bits
__device__ __forceinline__ void r8A_apply2(u64* v, const Coef2& k){
    bfly2(v[0],v[1],k.c1);  bfly2(v[2],v[3],k.c1);  bfly2(v[4],v[5],k.c1);  bfly2(v[6],v[7],k.c1);
    bfly2(v[0],v[2],k.cH);  bfly2(v[1],v[3],k.msH); bfly2(v[4],v[6],k.cH);  bfly2(v[5],v[7],k.msH);
    bfly2(v[0],v[4],k.q0);  bfly2(v[1],v[5],k.q1);  bfly2(v[2],v[6],k.q2);  bfly2(v[3],v[7],k.q3);
}
// Pass B: stages pair descending bits
__device__ __forceinline__ void r8B_apply2(u64* v, const Coef2& k){
    bfly2(v[0],v[4],k.c1);  bfly2(v[1],v[5],k.c1);  bfly2(v[2],v[6],k.c1);  bfly2(v[3],v[7],k.c1);
    bfly2(v[0],v[2],k.cH);  bfly2(v[1],v[3],k.cH);  bfly2(v[4],v[6],k.msH); bfly2(v[5],v[7],k.msH);
    bfly2(v[0],v[1],k.q0);  bfly2(v[2],v[3],k.q2);  bfly2(v[4],v[5],k.q1);  bfly2(v[6],v[7],k.q3);
}

template<int B>
__device__ __forceinline__ void r8A(float4* tile, int t){
    const int   j0   = t & ((1 << B) - 1);
    const int   base = ((t >> B) << (B + 3)) | j0;
    const float h4   = (float)j0 * (PI / (float)(4 << B));
    float s4 = sin_ap(h4), c4 = sin_ap(PIH - h4);
    Coef2 k = mkcoef2(pk(s4, s4), pk(c4, c4));
    int idx[8]; float4 v[8]; u64 xy[8], zw[8];
    #pragma unroll
    for (int n = 0; n < 8; n++){ idx[n] = swz(base + (n << B)); v[n] = tile[idx[n]]; }
    #pragma unroll
    for (int n = 0; n < 8; n++){ xy[n] = pk(v[n].x, v[n].y); zw[n] = pk(v[n].z, v[n].w); }
    r8A_apply2(xy, k);
    r8A_apply2(zw, k);
    #pragma unroll
    for (int n = 0; n < 8; n++){
        upk(v[n].x, v[n].y, xy[n]); upk(v[n].z, v[n].w, zw[n]);
        tile[idx[n]] = v[n];
    }
}

// packed pass-B round body on registers: lanes (x,y) use k01, (z,w) use k23
__device__ __forceinline__ void r8B_regs2(float4* v, const Coef2& k01, const Coef2& k23){
    u64 xy[8], zw[8];
    #pragma unroll
    for (int n = 0; n < 8; n++){ xy[n] = pk(v[n].x, v[n].y); zw[n] = pk(v[n].z, v[n].w); }
    r8B_apply2(xy, k01);
    r8B_apply2(zw, k23);
    #pragma unroll
    for (int n = 0; n < 8; n++){ upk(v[n].x, v[n].y, xy[n]); upk(v[n].z, v[n].w, zw[n]); }
}

template<int B>
__device__ __forceinline__ void r8B(float4* tile, int t, int R0){
    const int   mtop = (1 << (8 - B)) - 1;
    const int   base = ((t >> B) << (B + 3)) | (t & ((1 << B) - 1));
    const float sc   = PI / (float)(1 << (21 - B));
    const float cc   = 1.f - 0.5f * sc * sc;
    int   rl = (int)(__brev((unsigned)base) >> 21);
    int   jb = ((rl & mtop) << 11) + R0;
    float h0 = (float)jb * sc;
    int idx[8]; float4 v[8];
    #pragma unroll
    for (int n = 0; n < 8; n++){ idx[n] = swz(base + (n << B)); v[n] = tile[idx[n]]; }
    float s0 = sin_ap(h0), c0 = sin_ap(PIH - h0);
    float s1 = fmaf(c0, sc, s0 * cc), c1 = fmaf(-s0, sc, c0 * cc);
    float s2 = fmaf(c1, sc, s1 * cc), c2 = fmaf(-s1, sc, c1 * cc);
    float s3 = fmaf(c2, sc, s2 * cc), c3 = fmaf(-s2, sc, c2 * cc);
    Coef2 k01 = mkcoef2(pk(s0, s1), pk(c0, c1));
    Coef2 k23 = mkcoef2(pk(s2, s3), pk(c2, c3));
    r8B_regs2(v, k01, k23);
    #pragma unroll
    for (int n = 0; n < 8; n++) tile[idx[n]] = v[n];
}

// ================= Pass A: stages 1..11 =================
__global__ void __launch_bounds__(256, 4) fftA(const float4* __restrict__ x4){
    __shared__ float4 tile[2048];
    const int t   = threadIdx.x;
    const int lb4 = blockIdx.x;
    const int w   = t >> 5, ln = t & 31;

    // fused load + closed-form stages (1,2)
    #pragma unroll
    for (int m = 0; m < 2; m++){
        int g = (w << 6) | ln | (m << 5);
        int b = g << 2;
        float4 e0 = x4[(((int)(__brev((unsigned)(b + 0)) >> 21)) << 9) + lb4];
        float4 e1 = x4[(((int)(__brev((unsigned)(b + 1)) >> 21)) << 9) + lb4];
        float4 e2 = x4[(((int)(__brev((unsigned)(b + 2)) >> 21)) << 9) + lb4];
        float4 e3 = x4[(((int)(__brev((unsigned)(b + 3)) >> 21)) << 9) + lb4];
        float4 w0, w1, w2;
#define G12(L) { \
        float A  = fabsf(e0.L + e1.L), Bv = fabsf(e2.L + e3.L); \
        float d1 = e0.L - e1.L,        d2 = e2.L - e3.L;        \
        float s  = A + Bv,             q  = A - Bv;             \
        w0.L = s * s; w2.L = q * q; w1.L = fmaf(d1, d1, d2 * d2); }
        G12(x) G12(y) G12(z) G12(w)
#undef G12
        tile[swz(b)] = w0; tile[swz(b + 1)] = w1; tile[swz(b + 2)] = w2; tile[swz(b + 3)] = w1;
    }
    __syncwarp();

    r8A<2>(tile, t); __syncwarp();      // stages 3,4,5 (warp-local rows)
    r8A<5>(tile, t); __syncthreads();   // stages 6,7,8

    // stages 9,10,11 (B=8) fused with direct transposed store to scratch
    {
        const int   j0 = t & 255;
        const float h4 = (float)j0 * (PI / (float)(4 << 8));
        float s4 = sin_ap(h4), c4 = sin_ap(PIH - h4);
        Coef2 k = mkcoef2(pk(s4, s4), pk(c4, c4));
        float4 v[8]; u64 xy[8], zw[8];
        #pragma unroll
        for (int n = 0; n < 8; n++) v[n] = tile[swz(t + (n << 8))];
        #pragma unroll
        for (int n = 0; n < 8; n++){ xy[n] = pk(v[n].x, v[n].y); zw[n] = pk(v[n].z, v[n].w); }
        r8A_apply2(xy, k);
        r8A_apply2(zw, k);

        float* scrF = (float*)g_scr;
        const int base = ((t >> 2) << 13) + (lb4 << 4) + (t & 3);
        #pragma unroll
        for (int n = 0; n < 8; n++){
            float vx, vy, vz, vw;
            upk(vx, vy, xy[n]); upk(vz, vw, zw[n]);
            float* d = scrF + base + (n << 19);
            d[0]  = vx;
            d[4]  = vy;
            d[8]  = vz;
            d[12] = vw;
        }
    }
}

// ================= Pass B: stages 12..22 + sqrt + bit-reversed store =================
__global__ void __launch_bounds__(256, 4) fftB(float4* __restrict__ out4){
    __shared__ float4 tile[2048];
    const int t  = threadIdx.x;
    const int g  = blockIdx.x;
    const int R0 = g << 2;
    const int w  = t >> 5, ln = t & 31;

    // round 1 (stages 12,13,14): register-forwarded load (rows t + 256n)
    {
        const float sc = PI / (float)(1 << 13);
        const float cc = 1.f - 0.5f * sc * sc;
        float h0 = (float)R0 * sc;       // jb = R0
        float4 v[8];
        const float4* src = g_scr + ((long)g << 11) + t;
        #pragma unroll
        for (int n = 0; n < 8; n++) v[n] = src[n << 8];
        float s0 = sin_ap(h0), c0 = sin_ap(PIH - h0);
        float s1 = fmaf(c0, sc, s0 * cc), c1 = fmaf(-s0, sc, c0 * cc);
        float s2 = fmaf(c1, sc, s1 * cc), c2 = fmaf(-s1, sc, c1 * cc);
        float s3 = fmaf(c2, sc, s2 * cc), c3 = fmaf(-s2, sc, c2 * cc);
        Coef2 k01 = mkcoef2(pk(s0, s1), pk(c0, c1));
        Coef2 k23 = mkcoef2(pk(s2, s3), pk(c2, c3));
        r8B_regs2(v, k01, k23);
        #pragma unroll
        for (int n = 0; n < 8; n++) tile[swz(t + (n << 8))] = v[n];
    }
    __syncthreads();

    r8B<5>(tile, t, R0); __syncwarp();   // stages 15,16,17 (warp-local)
    r8B<2>(tile, t, R0); __syncwarp();   // stages 18,19,20 (warp-local)

    // final radix-4 (stages 21,22) + sqrt + bit-reversed scatter (packed)
    {
        const float hs = PI / (float)(1 << 21);
        #pragma unroll
        for (int m = 0; m < 2; m++){
            int gb   = (w << 6) | ln | (m << 5);
            int base = gb << 2;
            int i00 = swz(base), i01 = swz(base + 1), i10 = swz(base + 2), i11 = swz(base + 3);
            int rl = (int)(__brev((unsigned)base) >> 21);
            int jb = ((rl & 511) << 11) + R0;
            float h0 = (float)jb * hs;
            float4 v00 = tile[i00], v01 = tile[i01], v10 = tile[i10], v11 = tile[i11];
            float sh0 = sin_ap(h0), ch0 = sin_ap(PIH - h0);
            float sh1 = fmaf(ch0, hs, sh0), ch1 = fmaf(-sh0, hs, ch0);
            float sh2 = fmaf(ch1, hs, sh1), ch2 = fmaf(-sh1, hs, ch1);
            float sh3 = fmaf(ch2, hs, sh2), ch3 = fmaf(-sh2, hs, ch2);
            u64 a00, a01, a10, a11;
            // lanes (x,y)
            {
                u64 spk = pk(sh0, sh1), cpk = pk(ch0, ch1);
                u64 c2p = fma2(MTWO2, mul2(spk, spk), ONE2);
                u64 msp = mul2(MONE2, spk);
                a00 = pk(v00.x, v00.y); a01 = pk(v01.x, v01.y);
                a10 = pk(v10.x, v10.y); a11 = pk(v11.x, v11.y);
                bfly2(a00, a10, c2p); bfly2(a01, a11, c2p);
                bfly2(a00, a01, cpk); bfly2(a10, a11, msp);
                upk(v00.x, v00.y, a00); upk(v01.x, v01.y, a01);
                upk(v10.x, v10.y, a10); upk(v11.x, v11.y, a11);
            }
            // lanes (z,w)
            {
                u64 spk = pk(sh2, sh3), cpk = pk(ch2, ch3);
                u64 c2p = fma2(MTWO2, mul2(spk, spk), ONE2);
                u64 msp = mul2(MONE2, spk);
                a00 = pk(v00.z, v00.w); a01 = pk(v01.z, v01.w);
                a10 = pk(v10.z, v10.w); a11 = pk(v11.z, v11.w);
                bfly2(a00, a10, c2p); bfly2(a01, a11, c2p);
                bfly2(a00, a01, cpk); bfly2(a10, a11, msp);
                upk(v00.z, v00.w, a00); upk(v01.z, v01.w, a01);
                upk(v10.z, v10.w, a10); upk(v11.z, v11.w, a11);
            }
#define SQ4(v) make_float4(sqrt_ap(fmaxf(v.x,0.f)), sqrt_ap(fmaxf(v.y,0.f)), \
                           sqrt_ap(fmaxf(v.z,0.f)), sqrt_ap(fmaxf(v.w,0.f)))
            out4[(((int)(__brev((unsigned)(base + 0)) >> 21)) << 9) + g] = SQ4(v00);
            out4[(((int)(__brev((unsigned)(base + 1)) >> 21)) << 9) + g] = SQ4(v01);
            out4[(((int)(__brev((unsigned)(base + 2)) >> 21)) << 9) + g] = SQ4(v10);
            out4[(((int)(__brev((unsigned)(base + 3)) >> 21)) << 9) + g] = SQ4(v11);
#undef SQ4
        }
    }
}

extern "C" void kernel_launch(void* const* d_in, const int* in_sizes, int n_in,
                              void* d_out, int out_size) {
    const float4* x4 = (const float4*)d_in[0];
    fftA<<<512, 256>>>(x4);
    fftB<<<512, 256>>>((float4*)d_out);
}

// round 16
// speedup vs baseline: 1.0216x; 1.0216x over previous
#include <cuda_runtime.h>
#include <cstdint>

#define PI  3.14159265358979323846f
#define PIH 1.57079632679489662f
#define IR2 0.70710678118654752f

typedef unsigned long long u64;

#define ONE2   0x3F8000003F800000ull
#define MONE2  0xBF800000BF800000ull
#define TWO2   0x4000000040000000ull
#define MTWO2  0xC0000000C0000000ull
#define IR22   0x3F3504F33F3504F3ull
#define MIR22  0xBF3504F3BF3504F3ull

__device__ float4 g_scr[1 << 20];

__device__ __forceinline__ float sin_ap(float x){ float y; asm("sin.approx.f32 %0, %1;" : "=f"(y) : "f"(x)); return y; }
__device__ __forceinline__ float sqrt_ap(float x){ float y; asm("sqrt.approx.f32 %0, %1;" : "=f"(y) : "f"(x)); return y; }
// Newton sqrt on the fma/alu pipes (x must be >= ~1e-35; err ~1e-6)
__device__ __forceinline__ float sqrt_nr(float x){
    float y  = __int_as_float(0x5f3759df - (__float_as_int(x) >> 1));
    float hx = 0.5f * x;
    y = y * fmaf(-hx * y, y, 1.5f);
    y = y * fmaf(-hx * y, y, 1.5f);
    return x * y;
}
__device__ __forceinline__ u64 pk(float lo, float hi){ u64 r; asm("mov.b64 %0, {%1, %2};" : "=l"(r) : "f"(lo), "f"(hi)); return r; }
__device__ __forceinline__ void upk(float& lo, float& hi, u64 v){ asm("mov.b64 {%0, %1}, %2;" : "=f"(lo), "=f"(hi) : "l"(v)); }
__device__ __forceinline__ u64 mul2(u64 a, u64 b){ u64 d; asm("mul.rn.f32x2 %0, %1, %2;" : "=l"(d) : "l"(a), "l"(b)); return d; }
__device__ __forceinline__ u64 add2(u64 a, u64 b){ u64 d; asm("add.rn.f32x2 %0, %1, %2;" : "=l"(d) : "l"(a), "l"(b)); return d; }
__device__ __forceinline__ u64 fma2(u64 a, u64 b, u64 c){ u64 d; asm("fma.rn.f32x2 %0, %1, %2, %3;" : "=l"(d) : "l"(a), "l"(b), "l"(c)); return d; }

__device__ __forceinline__ int swz(int r){ return r ^ ((r >> 4) & 3) ^ (((r >> 5) & 3) << 2); }

// packed butterfly, both sqrts on MUFU
__device__ __forceinline__ void bfly2(u64& Se, u64& So, u64 c){
    u64 p = mul2(Se, So);
    float px, py; upk(px, py, p);
    float rx = sqrt_ap(fmaxf(px, 0.f));
    float ry = sqrt_ap(fmaxf(py, 0.f));
    u64 T  = mul2(c, pk(rx, ry));
    u64 Sp = add2(Se, So);
    Se = fma2(TWO2,  T, Sp);
    So = fma2(MTWO2, T, Sp);
}
// hybrid: lane lo on MUFU, lane hi on fma-pipe Newton
__device__ __forceinline__ void bfly2h(u64& Se, u64& So, u64 c){
    u64 p = mul2(Se, So);
    float px, py; upk(px, py, p);
    float rx = sqrt_ap(fmaxf(px, 0.f));
    float ry = sqrt_nr(fmaxf(py, 1e-35f));
    u64 T  = mul2(c, pk(rx, ry));
    u64 Sp = add2(Se, So);
    Se = fma2(TWO2,  T, Sp);
    So = fma2(MTWO2, T, Sp);
}

struct Coef2 { u64 c1, cH, msH, q0, q1, q2, q3; };

__device__ __forceinline__ Coef2 mkcoef2(u64 s4, u64 c4){
    Coef2 k;
    u64 t  = mul2(s4, c4);
    u64 sH = add2(t, t);
    u64 cH = fma2(MTWO2, mul2(s4, s4), ONE2);
    k.c1  = fma2(TWO2, mul2(cH, cH), MONE2);
    k.cH  = cH;
    k.msH = mul2(MONE2, sH);
    k.q0  = c4;
    u64 ms4 = mul2(MONE2, s4);
    k.q1  = mul2(add2(c4, ms4), IR22);
    k.q2  = ms4;
    k.q3  = mul2(add2(c4, s4), MIR22);
    return k;
}

// Pass A orders (ascending bits); pure-MUFU and hybrid variants
__device__ __forceinline__ void r8A_apply2(u64* v, const Coef2& k){
    bfly2(v[0],v[1],k.c1);  bfly2(v[2],v[3],k.c1);  bfly2(v[4],v[5],k.c1);  bfly2(v[6],v[7],k.c1);
    bfly2(v[0],v[2],k.cH);  bfly2(v[1],v[3],k.msH); bfly2(v[4],v[6],k.cH);  bfly2(v[5],v[7],k.msH);
    bfly2(v[0],v[4],k.q0);  bfly2(v[1],v[5],k.q1);  bfly2(v[2],v[6],k.q2);  bfly2(v[3],v[7],k.q3);
}
__device__ __forceinline__ void r8A_apply2h(u64* v, const Coef2& k){
    bfly2h(v[0],v[1],k.c1);  bfly2h(v[2],v[3],k.c1);  bfly2h(v[4],v[5],k.c1);  bfly2h(v[6],v[7],k.c1);
    bfly2h(v[0],v[2],k.cH);  bfly2h(v[1],v[3],k.msH); bfly2h(v[4],v[6],k.cH);  bfly2h(v[5],v[7],k.msH);
    bfly2h(v[0],v[4],k.q0);  bfly2h(v[1],v[5],k.q1);  bfly2h(v[2],v[6],k.q2);  bfly2h(v[3],v[7],k.q3);
}
// Pass B orders (descending bits)
__device__ __forceinline__ void r8B_apply2(u64* v, const Coef2& k){
    bfly2(v[0],v[4],k.c1);  bfly2(v[1],v[5],k.c1);  bfly2(v[2],v[6],k.c1);  bfly2(v[3],v[7],k.c1);
    bfly2(v[0],v[2],k.cH);  bfly2(v[1],v[3],k.cH);  bfly2(v[4],v[6],k.msH); bfly2(v[5],v[7],k.msH);
    bfly2(v[0],v[1],k.q0);  bfly2(v[2],v[3],k.q2);  bfly2(v[4],v[5],k.q1);  bfly2(v[6],v[7],k.q3);
}
__device__ __forceinline__ void r8B_apply2h(u64* v, const Coef2& k){
    bfly2h(v[0],v[4],k.c1);  bfly2h(v[1],v[5],k.c1);  bfly2h(v[2],v[6],k.c1);  bfly2h(v[3],v[7],k.c1);
    bfly2h(v[0],v[2],k.cH);  bfly2h(v[1],v[3],k.cH);  bfly2h(v[4],v[6],k.msH); bfly2h(v[5],v[7],k.msH);
    bfly2h(v[0],v[1],k.q0);  bfly2h(v[2],v[3],k.q2);  bfly2h(v[4],v[5],k.q1);  bfly2h(v[6],v[7],k.q3);
}

template<int B>
__device__ __forceinline__ void r8A(float4* tile, int t){
    const int   j0   = t & ((1 << B) - 1);
    const int   base = ((t >> B) << (B + 3)) | j0;
    const float h4   = (float)j0 * (PI / (float)(4 << B));
    float s4 = sin_ap(h4), c4 = sin_ap(PIH - h4);
    Coef2 k = mkcoef2(pk(s4, s4), pk(c4, c4));
    int idx[8]; float4 v[8]; u64 xy[8], zw[8];
    #pragma unroll
    for (int n = 0; n < 8; n++){ idx[n] = swz(base + (n << B)); v[n] = tile[idx[n]]; }
    #pragma unroll
    for (int n = 0; n < 8; n++){ xy[n] = pk(v[n].x, v[n].y); zw[n] = pk(v[n].z, v[n].w); }
    r8A_apply2(xy, k);
    r8A_apply2h(zw, k);
    #pragma unroll
    for (int n = 0; n < 8; n++){
        upk(v[n].x, v[n].y, xy[n]); upk(v[n].z, v[n].w, zw[n]);
        tile[idx[n]] = v[n];
    }
}

__device__ __forceinline__ void r8B_regs2(float4* v, const Coef2& k01, const Coef2& k23){
    u64 xy[8], zw[8];
    #pragma unroll
    for (int n = 0; n < 8; n++){ xy[n] = pk(v[n].x, v[n].y); zw[n] = pk(v[n].z, v[n].w); }
    r8B_apply2(xy, k01);
    r8B_apply2h(zw, k23);
    #pragma unroll
    for (int n = 0; n < 8; n++){ upk(v[n].x, v[n].y, xy[n]); upk(v[n].z, v[n].w, zw[n]); }
}

template<int B>
__device__ __forceinline__ void r8B(float4* tile, int t, int R0){
    const int   mtop = (1 << (8 - B)) - 1;
    const int   base = ((t >> B) << (B + 3)) | (t & ((1 << B) - 1));
    const float sc   = PI / (float)(1 << (21 - B));
    const float cc   = 1.f - 0.5f * sc * sc;
    int   rl = (int)(__brev((unsigned)base) >> 21);
    int   jb = ((rl & mtop) << 11) + R0;
    float h0 = (float)jb * sc;
    int idx[8]; float4 v[8];
    #pragma unroll
    for (int n = 0; n < 8; n++){ idx[n] = swz(base + (n << B)); v[n] = tile[idx[n]]; }
    float s0 = sin_ap(h0), c0 = sin_ap(PIH - h0);
    float s1 = fmaf(c0, sc, s0 * cc), c1 = fmaf(-s0, sc, c0 * cc);
    float s2 = fmaf(c1, sc, s1 * cc), c2 = fmaf(-s1, sc, c1 * cc);
    float s3 = fmaf(c2, sc, s2 * cc), c3 = fmaf(-s2, sc, c2 * cc);
    Coef2 k01 = mkcoef2(pk(s0, s1), pk(c0, c1));
    Coef2 k23 = mkcoef2(pk(s2, s3), pk(c2, c3));
    r8B_regs2(v, k01, k23);
    #pragma unroll
    for (int n = 0; n < 8; n++) tile[idx[n]] = v[n];
}

// ================= Pass A: stages 1..11 =================
__global__ void __launch_bounds__(256, 4) fftA(const float4* __restrict__ x4){
    __shared__ float4 tile[2048];
    const int t   = threadIdx.x;
    const int lb4 = blockIdx.x;
    const int w   = t >> 5, ln = t & 31;

    #pragma unroll
    for (int m = 0; m < 2; m++){
        int g = (w << 6) | ln | (m << 5);
        int b = g << 2;
        float4 e0 = x4[(((int)(__brev((unsigned)(b + 0)) >> 21)) << 9) + lb4];
        float4 e1 = x4[(((int)(__brev((unsigned)(b + 1)) >> 21)) << 9) + lb4];
        float4 e2 = x4[(((int)(__brev((unsigned)(b + 2)) >> 21)) << 9) + lb4];
        float4 e3 = x4[(((int)(__brev((unsigned)(b + 3)) >> 21)) << 9) + lb4];
        float4 w0, w1, w2;
#define G12(L) { \
        float A  = fabsf(e0.L + e1.L), Bv = fabsf(e2.L + e3.L); \
        float d1 = e0.L - e1.L,        d2 = e2.L - e3.L;        \
        float s  = A + Bv,             q  = A - Bv;             \
        w0.L = s * s; w2.L = q * q; w1.L = fmaf(d1, d1, d2 * d2); }
        G12(x) G12(y) G12(z) G12(w)
#undef G12
        tile[swz(b)] = w0; tile[swz(b + 1)] = w1; tile[swz(b + 2)] = w2; tile[swz(b + 3)] = w1;
    }
    __syncwarp();

    r8A<2>(tile, t); __syncwarp();      // stages 3,4,5
    r8A<5>(tile, t); __syncthreads();   // stages 6,7,8

    // stages 9,10,11 fused with direct transposed store to scratch
    {
        const int   j0 = t & 255;
        const float h4 = (float)j0 * (PI / (float)(4 << 8));
        float s4 = sin_ap(h4), c4 = sin_ap(PIH - h4);
        Coef2 k = mkcoef2(pk(s4, s4), pk(c4, c4));
        float4 v[8]; u64 xy[8], zw[8];
        #pragma unroll
        for (int n = 0; n < 8; n++) v[n] = tile[swz(t + (n << 8))];
        #pragma unroll
        for (int n = 0; n < 8; n++){ xy[n] = pk(v[n].x, v[n].y); zw[n] = pk(v[n].z, v[n].w); }
        r8A_apply2(xy, k);
        r8A_apply2h(zw, k);

        float* scrF = (float*)g_scr;
        const int base = ((t >> 2) << 13) + (lb4 << 4) + (t & 3);
        #pragma unroll
        for (int n = 0; n < 8; n++){
            float vx, vy, vz, vw;
            upk(vx, vy, xy[n]); upk(vz, vw, zw[n]);
            float* d = scrF + base + (n << 19);
            d[0]  = vx;
            d[4]  = vy;
            d[8]  = vz;
            d[12] = vw;
        }
    }
}

// ================= Pass B: stages 12..22 + sqrt + bit-reversed store =================
__global__ void __launch_bounds__(256, 4) fftB(float4* __restrict__ out4){
    __shared__ float4 tile[2048];
    const int t  = threadIdx.x;
    const int g  = blockIdx.x;
    const int R0 = g << 2;
    const int w  = t >> 5, ln = t & 31;

    // round 1 (stages 12,13,14)
    {
        const float sc = PI / (float)(1 << 13);
        const float cc = 1.f - 0.5f * sc * sc;
        float h0 = (float)R0 * sc;
        float4 v[8];
        const float4* src = g_scr + ((long)g << 11) + t;
        #pragma unroll
        for (int n = 0; n < 8; n++) v[n] = src[n << 8];
        float s0 = sin_ap(h0), c0 = sin_ap(PIH - h0);
        float s1 = fmaf(c0, sc, s0 * cc), c1 = fmaf(-s0, sc, c0 * cc);
        float s2 = fmaf(c1, sc, s1 * cc), c2 = fmaf(-s1, sc, c1 * cc);
        float s3 = fmaf(c2, sc, s2 * cc), c3 = fmaf(-s2, sc, c2 * cc);
        Coef2 k01 = mkcoef2(pk(s0, s1), pk(c0, c1));
        Coef2 k23 = mkcoef2(pk(s2, s3), pk(c2, c3));
        r8B_regs2(v, k01, k23);
        #pragma unroll
        for (int n = 0; n < 8; n++) tile[swz(t + (n << 8))] = v[n];
    }
    __syncthreads();

    r8B<5>(tile, t, R0); __syncwarp();
    r8B<2>(tile, t, R0); __syncwarp();

    // final radix-4 (stages 21,22) + sqrt + bit-reversed scatter
    {
        const float hs = PI / (float)(1 << 21);
        #pragma unroll
        for (int m = 0; m < 2; m++){
            int gb   = (w << 6) | ln | (m << 5);
            int base = gb << 2;
            int i00 = swz(base), i01 = swz(base + 1), i10 = swz(base + 2), i11 = swz(base + 3);
            int rl = (int)(__brev((unsigned)base) >> 21);
            int jb = ((rl & 511) << 11) + R0;
            float h0 = (float)jb * hs;
            float4 v00 = tile[i00], v01 = tile[i01], v10 = tile[i10], v11 = tile[i11];
            float sh0 = sin_ap(h0), ch0 = sin_ap(PIH - h0);
            float sh1 = fmaf(ch0, hs, sh0), ch1 = fmaf(-sh0, hs, ch0);
            float sh2 = fmaf(ch1, hs, sh1), ch2 = fmaf(-sh1, hs, ch1);
            float sh3 = fmaf(ch2, hs, sh2), ch3 = fmaf(-sh2, hs, ch2);
            u64 a00, a01, a10, a11;
            // lanes (x,y): pure MUFU
            {
                u64 spk = pk(sh0, sh1), cpk = pk(ch0, ch1);
                u64 c2p = fma2(MTWO2, mul2(spk, spk), ONE2);
                u64 msp = mul2(MONE2, spk);
                a00 = pk(v00.x, v00.y); a01 = pk(v01.x, v01.y);
                a10 = pk(v10.x, v10.y); a11 = pk(v11.x, v11.y);
                bfly2(a00, a10, c2p); bfly2(a01, a11, c2p);
                bfly2(a00, a01, cpk); bfly2(a10, a11, msp);
                upk(v00.x, v00.y, a00); upk(v01.x, v01.y, a01);
                upk(v10.x, v10.y, a10); upk(v11.x, v11.y, a11);
            }
            // lanes (z,w): hybrid
            {
                u64 spk = pk(sh2, sh3), cpk = pk(ch2, ch3);
                u64 c2p = fma2(MTWO2, mul2(spk, spk), ONE2);
                u64 msp = mul2(MONE2, spk);
                a00 = pk(v00.z, v00.w); a01 = pk(v01.z, v01.w);
                a10 = pk(v10.z, v10.w); a11 = pk(v11.z, v11.w);
                bfly2h(a00, a10, c2p); bfly2h(a01, a11, c2p);
                bfly2h(a00, a01, cpk); bfly2h(a10, a11, msp);
                upk(v00.z, v00.w, a00); upk(v01.z, v01.w, a01);
                upk(v10.z, v10.w, a10); upk(v11.z, v11.w, a11);
            }
#define SQ4(v) make_float4(sqrt_ap(fmaxf(v.x,0.f)), sqrt_ap(fmaxf(v.y,0.f)), \
                           sqrt_nr(fmaxf(v.z,1e-35f)), sqrt_nr(fmaxf(v.w,1e-35f)))
            out4[(((int)(__brev((unsigned)(base + 0)) >> 21)) << 9) + g] = SQ4(v00);
            out4[(((int)(__brev((unsigned)(base + 1)) >> 21)) << 9) + g] = SQ4(v01);
            out4[(((int)(__brev((unsigned)(base + 2)) >> 21)) << 9) + g] = SQ4(v10);
            out4[(((int)(__brev((unsigned)(base + 3)) >> 21)) << 9) + g] = SQ4(v11);
#undef SQ4
        }
    }
}

extern "C" void kernel_launch(void* const* d_in, const int* in_sizes, int n_in,
                              void* d_out, int out_size) {
    const float4* x4 = (const float4*)d_in[0];
    fftA<<<512, 256>>>(x4);
    fftB<<<512, 256>>>((float4*)d_out);
}